// round 14
// baseline (speedup 1.0000x reference)
#include <cuda_runtime.h>
#include <cstdint>
#include <cstddef>

// ---------------- Problem constants ----------------
#define BB   8
#define NN   1024
#define DIMC 512
#define HH   8
#define DD   64
#define RR   64          // R1 = R2 = R = 64
#define MTOT (BB*NN)     // 8192
#define SCALE_ATT 0.125f // D^-0.5
#define S_CONST 1.0f

// ---------------- Scratch (__device__ globals; no allocation allowed) ----------------
__device__ float g_qkv  [(size_t)MTOT*3*DIMC];
__device__ float g_att  [(size_t)MTOT*DIMC];   // stored pre-rounded to tf32 bits
__device__ float g_CPc  [4*RR*RR];             // [f][ij]
__device__ float g_WT   [(3*DIMC+DIMC)*RR];    // rows 0..1535: WbigT, 1536..2047: WpT (xS)
__device__ float g_Wc   [(size_t)(3*DIMC+DIMC)*DIMC]; // tf32-rounded combined weights
__device__ float g_bqc  [3*DIMC];
__device__ float g_bpc  [DIMC];

// ---------------- Small precompute kernels ----------------
__global__ void cpc_kernel(const float* __restrict__ CP_C, const float* __restrict__ CP_att) {
    __shared__ float att_s[RR * 4];
    int tid = threadIdx.x;
    att_s[tid] = CP_att[tid];
    __syncthreads();
    int ij = blockIdx.x * 256 + tid;
    const float4* row = (const float4*)&CP_C[(size_t)ij << 6];
    float a0 = 0.f, a1 = 0.f, a2 = 0.f, a3 = 0.f;
    #pragma unroll
    for (int r4 = 0; r4 < 16; r4++) {
        float4 v = row[r4];
        const float* at = &att_s[r4 * 16];
        a0 += v.x * at[0]  + v.y * at[4]  + v.z * at[8]  + v.w * at[12];
        a1 += v.x * at[1]  + v.y * at[5]  + v.z * at[9]  + v.w * at[13];
        a2 += v.x * at[2]  + v.y * at[6]  + v.z * at[10] + v.w * at[14];
        a3 += v.x * at[3]  + v.y * at[7]  + v.z * at[11] + v.w * at[15];
    }
    g_CPc[0 * 4096 + ij] = a0;
    g_CPc[1 * 4096 + ij] = a1;
    g_CPc[2 * 4096 + ij] = a2;
    g_CPc[3 * 4096 + ij] = a3;
}

__global__ void wfac_kernel(const float* __restrict__ CP_V_w) {
    int idx = blockIdx.x * 256 + threadIdx.x;   // 131072
    int r = idx & 63;
    int o = idx >> 6;                           // 0..2047
    int f, d;
    if (o < 3 * DIMC) { f = o >> 9; d = o & 511; }
    else              { f = 3;      d = o - 3 * DIMC; }
    const float4* cp = (const float4*)&g_CPc[f * 4096 + r * RR];
    const float4* vw = (const float4*)&CP_V_w[(size_t)d * RR];
    float s = 0.f;
    #pragma unroll
    for (int i = 0; i < 16; i++) {
        float4 a = cp[i], b = vw[i];
        s += a.x * b.x + a.y * b.y + a.z * b.z + a.w * b.w;
    }
    g_WT[o * RR + r] = (o < 3 * DIMC) ? s : s * S_CONST;
}

__global__ void biascomb_kernel(const float* __restrict__ CP_U_b,
                                const float* __restrict__ CP_V_b,
                                const float* __restrict__ proj_b) {
    int w = blockIdx.x * 8 + (threadIdx.x >> 5);  // 0..2047
    int lane = threadIdx.x & 31;
    const float* row = &g_WT[w * RR];
    float s = CP_U_b[lane] * row[lane] + CP_U_b[lane + 32] * row[lane + 32];
    #pragma unroll
    for (int off = 16; off > 0; off >>= 1)
        s += __shfl_down_sync(0xffffffffu, s, off);
    if (lane == 0) {
        if (w < 3 * DIMC) g_bqc[w] = CP_V_b[w & 511] + s;
        else {
            int d = w - 3 * DIMC;
            g_bpc[d] = proj_b[d] + S_CONST * CP_V_b[d] + s;
        }
    }
}

// ---------------- tf32 helpers ----------------
__device__ __forceinline__ uint32_t f2tf(float x) {
    uint32_t r;
    asm("cvt.rna.tf32.f32 %0, %1;" : "=r"(r) : "f"(x));
    return r;
}
#define TF_RND 0x1000u   // RNA emulation for raw fp32 bits fed to tf32 mma

__device__ __forceinline__ void mma_tf32(float c[4], uint32_t a0, uint32_t a1,
                                         uint32_t a2, uint32_t a3,
                                         uint32_t b0, uint32_t b1) {
    asm volatile(
        "mma.sync.aligned.m16n8k8.row.col.f32.tf32.tf32.f32 "
        "{%0,%1,%2,%3}, {%4,%5,%6,%7}, {%8,%9}, {%0,%1,%2,%3};\n"
        : "+f"(c[0]), "+f"(c[1]), "+f"(c[2]), "+f"(c[3])
        : "r"(a0), "r"(a1), "r"(a2), "r"(a3), "r"(b0), "r"(b1));
}

__device__ __forceinline__ void cp_async16(uint32_t smem_addr, const void* gptr) {
    asm volatile("cp.async.ca.shared.global [%0], [%1], 16;\n"
                 :: "r"(smem_addr), "l"(gptr));
}
__device__ __forceinline__ void cp_async16_cg(uint32_t smem_addr, const void* gptr) {
    asm volatile("cp.async.cg.shared.global [%0], [%1], 16;\n"
                 :: "r"(smem_addr), "l"(gptr));
}
__device__ __forceinline__ uint32_t smem_u32(const void* p) {
    return (uint32_t)__cvta_generic_to_shared(p);
}

extern __shared__ float dyn_sm[];

// ---------------- cp.async 3-stage tf32 GEMM, BK=32 (B in [N,K], tf32-prerounded B) ----------------
// RA=1: round A fragments in-loop (A is raw fp32, e.g. x). RA=0: A already tf32-rounded.
#define GST 36
#define STAGE_W (128*GST)
#define GEMM_NK_SMEM ((3*STAGE_W*2) * 4)

template<int RA>
__global__ __launch_bounds__(256, 2)
void gemm_nk_async(const float* __restrict__ A, int lda,
                   const float* __restrict__ B, int K,
                   const float* __restrict__ bias,
                   float* __restrict__ C, int N) {
    float* As = dyn_sm;
    float* Bs = dyn_sm + 3 * STAGE_W;

    int tid  = threadIdx.x;
    int lane = tid & 31;
    int warp = tid >> 5;
    int warp_m = (warp >> 2) * 64;
    int warp_n = (warp & 3) * 32;
    int bm0 = blockIdx.y * 128;
    int bn0 = blockIdx.x * 128;
    int lr = lane >> 2;
    int lc = lane & 3;

    float acc[4][4][4];
    #pragma unroll
    for (int i = 0; i < 4; i++)
        #pragma unroll
        for (int j = 0; j < 4; j++)
            #pragma unroll
            for (int k = 0; k < 4; k++) acc[i][j][k] = 0.f;

    // loaders: each thread owns one row-half of 16 floats (4 chunks) per operand
    int a_m = tid >> 1;                 // 0..127
    int a_c = (tid & 1) * 16;           // 0 or 16
    const float* pa = &A[(size_t)(bm0 + a_m) * lda + a_c];
    uint32_t sa = smem_u32(&As[a_m * GST + a_c]);

    int b_n = tid >> 1;                 // 0..127
    int b_c = (tid & 1) * 16;
    const float* pb = &B[(size_t)(bn0 + b_n) * K + b_c];
    uint32_t sb = smem_u32(&Bs[b_n * GST + b_c]);

    const uint32_t stage_bytes = STAGE_W * 4;

    // prologue: stages 0,1
    #pragma unroll
    for (int s = 0; s < 2; s++) {
        int k0 = s * 32;
        #pragma unroll
        for (int j = 0; j < 4; j++) {
            cp_async16_cg(sa + s * stage_bytes + j * 16, pa + k0 + j * 4);
            cp_async16_cg(sb + s * stage_bytes + j * 16, pb + k0 + j * 4);
        }
        asm volatile("cp.async.commit_group;\n" ::);
    }

    int T = K / 32;
    uint32_t* Asu = (uint32_t*)As;
    uint32_t* Bsu = (uint32_t*)Bs;

    #pragma unroll 1
    for (int t = 0; t < T; t++) {
        int p = t % 3;
        asm volatile("cp.async.wait_group 1;\n" ::);
        __syncthreads();

        int tn = t + 2;
        if (tn < T) {
            int s = tn % 3;
            int k0 = tn * 32;
            #pragma unroll
            for (int j = 0; j < 4; j++) {
                cp_async16_cg(sa + s * stage_bytes + j * 16, pa + k0 + j * 4);
                cp_async16_cg(sb + s * stage_bytes + j * 16, pb + k0 + j * 4);
            }
        }
        asm volatile("cp.async.commit_group;\n" ::);

        int pbase = p * STAGE_W;
        #pragma unroll
        for (int kk = 0; kk < 32; kk += 8) {
            uint32_t af[4][4], bf[4][2];
            #pragma unroll
            for (int mt = 0; mt < 4; mt++) {
                int r = warp_m + mt * 16 + lr;
                af[mt][0] = Asu[pbase + r * GST + kk + lc];
                af[mt][1] = Asu[pbase + (r + 8) * GST + kk + lc];
                af[mt][2] = Asu[pbase + r * GST + kk + 4 + lc];
                af[mt][3] = Asu[pbase + (r + 8) * GST + kk + 4 + lc];
                if (RA) {
                    af[mt][0] += TF_RND; af[mt][1] += TF_RND;
                    af[mt][2] += TF_RND; af[mt][3] += TF_RND;
                }
            }
            #pragma unroll
            for (int nt = 0; nt < 4; nt++) {
                int c = warp_n + nt * 8 + lr;
                bf[nt][0] = Bsu[pbase + c * GST + kk + lc];
                bf[nt][1] = Bsu[pbase + c * GST + kk + 4 + lc];
            }
            #pragma unroll
            for (int mt = 0; mt < 4; mt++)
                #pragma unroll
                for (int nt = 0; nt < 4; nt++)
                    mma_tf32(acc[mt][nt], af[mt][0], af[mt][1], af[mt][2], af[mt][3],
                             bf[nt][0], bf[nt][1]);
        }
    }

    #pragma unroll
    for (int mt = 0; mt < 4; mt++) {
        int row = bm0 + warp_m + mt * 16 + lr;
        #pragma unroll
        for (int nt = 0; nt < 4; nt++) {
            int col = bn0 + warp_n + nt * 8 + lc * 2;
            float b0 = bias[col], b1 = bias[col + 1];
            *(float2*)&C[(size_t)row * N + col] =
                make_float2(acc[mt][nt][0] + b0, acc[mt][nt][1] + b1);
            *(float2*)&C[(size_t)(row + 8) * N + col] =
                make_float2(acc[mt][nt][2] + b0, acc[mt][nt][3] + b1);
        }
    }
}

// ---------------- Combine GEMM (B in [K,N], split Cadd; output tf32-rounded) ----------------
__global__ __launch_bounds__(256, 2)
void gemm_kn(const float* __restrict__ A, int lda,
             const float* __restrict__ B, int K,
             const float* __restrict__ Cadd, const float* __restrict__ Cadd2,
             int cadd_split,
             float* __restrict__ C, int N) {
    __shared__ uint32_t As[2][128][20];
    __shared__ uint32_t Bs[2][128][20];

    int tid  = threadIdx.x;
    int lane = tid & 31;
    int warp = tid >> 5;
    int warp_m = (warp >> 2) * 64;
    int warp_n = (warp & 3) * 32;
    int bm0 = blockIdx.y * 128;
    int bn0 = blockIdx.x * 128;
    int lr = lane >> 2;
    int lc = lane & 3;

    float acc[4][4][4];
    #pragma unroll
    for (int i = 0; i < 4; i++)
        #pragma unroll
        for (int j = 0; j < 4; j++)
            #pragma unroll
            for (int k = 0; k < 4; k++) acc[i][j][k] = 0.f;

    int a_m = tid >> 2;
    int a_k = (tid & 3) * 4;
    const float* pa0 = &A[(size_t)(bm0 + a_m) * lda + a_k];
    const float* pa1 = &A[(size_t)(bm0 + a_m + 64) * lda + a_k];

    int bkn_k = tid >> 4;
    int bkn_n = (tid & 15) * 8;
    const float* pb_kn = &B[(size_t)bkn_k * N + bn0 + bkn_n];

    float4 av0, av1, bv0, bv1;
    av0 = *(const float4*)pa0;
    av1 = *(const float4*)pa1;
    bv0 = *(const float4*)pb_kn;
    bv1 = *(const float4*)(pb_kn + 4);
    {
        *(uint4*)&As[0][a_m][a_k]      = make_uint4(f2tf(av0.x), f2tf(av0.y), f2tf(av0.z), f2tf(av0.w));
        *(uint4*)&As[0][a_m + 64][a_k] = make_uint4(f2tf(av1.x), f2tf(av1.y), f2tf(av1.z), f2tf(av1.w));
        Bs[0][bkn_n + 0][bkn_k] = f2tf(bv0.x);
        Bs[0][bkn_n + 1][bkn_k] = f2tf(bv0.y);
        Bs[0][bkn_n + 2][bkn_k] = f2tf(bv0.z);
        Bs[0][bkn_n + 3][bkn_k] = f2tf(bv0.w);
        Bs[0][bkn_n + 4][bkn_k] = f2tf(bv1.x);
        Bs[0][bkn_n + 5][bkn_k] = f2tf(bv1.y);
        Bs[0][bkn_n + 6][bkn_k] = f2tf(bv1.z);
        Bs[0][bkn_n + 7][bkn_k] = f2tf(bv1.w);
    }
    __syncthreads();

    int T = K / 16;
    #pragma unroll 1
    for (int t = 0; t < T; t++) {
        int p = t & 1;
        if (t + 1 < T) {
            int k0 = (t + 1) * 16;
            av0 = *(const float4*)(pa0 + k0);
            av1 = *(const float4*)(pa1 + k0);
            bv0 = *(const float4*)(pb_kn + (size_t)k0 * N);
            bv1 = *(const float4*)(pb_kn + (size_t)k0 * N + 4);
        }

        #pragma unroll
        for (int kk = 0; kk < 16; kk += 8) {
            uint32_t af[4][4], bf[4][2];
            #pragma unroll
            for (int mt = 0; mt < 4; mt++) {
                int r = warp_m + mt * 16 + lr;
                af[mt][0] = As[p][r][kk + lc];
                af[mt][1] = As[p][r + 8][kk + lc];
                af[mt][2] = As[p][r][kk + 4 + lc];
                af[mt][3] = As[p][r + 8][kk + 4 + lc];
            }
            #pragma unroll
            for (int nt = 0; nt < 4; nt++) {
                int c = warp_n + nt * 8 + lr;
                bf[nt][0] = Bs[p][c][kk + lc];
                bf[nt][1] = Bs[p][c][kk + 4 + lc];
            }
            #pragma unroll
            for (int mt = 0; mt < 4; mt++)
                #pragma unroll
                for (int nt = 0; nt < 4; nt++)
                    mma_tf32(acc[mt][nt], af[mt][0], af[mt][1], af[mt][2], af[mt][3],
                             bf[nt][0], bf[nt][1]);
        }

        if (t + 1 < T) {
            int q = 1 - p;
            *(uint4*)&As[q][a_m][a_k]      = make_uint4(f2tf(av0.x), f2tf(av0.y), f2tf(av0.z), f2tf(av0.w));
            *(uint4*)&As[q][a_m + 64][a_k] = make_uint4(f2tf(av1.x), f2tf(av1.y), f2tf(av1.z), f2tf(av1.w));
            Bs[q][bkn_n + 0][bkn_k] = f2tf(bv0.x);
            Bs[q][bkn_n + 1][bkn_k] = f2tf(bv0.y);
            Bs[q][bkn_n + 2][bkn_k] = f2tf(bv0.z);
            Bs[q][bkn_n + 3][bkn_k] = f2tf(bv0.w);
            Bs[q][bkn_n + 4][bkn_k] = f2tf(bv1.x);
            Bs[q][bkn_n + 5][bkn_k] = f2tf(bv1.y);
            Bs[q][bkn_n + 6][bkn_k] = f2tf(bv1.z);
            Bs[q][bkn_n + 7][bkn_k] = f2tf(bv1.w);
        }
        __syncthreads();
    }

    // Epilogue: split Cadd add, then round to tf32 bits (these feed mma B later)
    #pragma unroll
    for (int mt = 0; mt < 4; mt++) {
        int row = bm0 + warp_m + mt * 16 + lr;
        #pragma unroll
        for (int nt = 0; nt < 4; nt++) {
            int col = bn0 + warp_n + nt * 8 + lc * 2;
            const float* ca  = (row < cadd_split) ? &Cadd[(size_t)row * N]
                                                  : &Cadd2[(size_t)(row - cadd_split) * N];
            const float* ca8 = (row < cadd_split) ? &Cadd[(size_t)(row + 8) * N]
                                                  : &Cadd2[(size_t)(row + 8 - cadd_split) * N];
            float2 c0 = *(const float2*)&ca[col];
            float2 c1 = *(const float2*)&ca8[col];
            uint2 v0 = make_uint2(f2tf(acc[mt][nt][0] + c0.x), f2tf(acc[mt][nt][1] + c0.y));
            uint2 v1 = make_uint2(f2tf(acc[mt][nt][2] + c1.x), f2tf(acc[mt][nt][3] + c1.y));
            *(uint2*)&C[(size_t)row * N + col] = v0;
            *(uint2*)&C[(size_t)(row + 8) * N + col] = v1;
        }
    }
}

// ---------------- Tensor-core flash attention (double-buffered K/V cp.async) ----------------
#define SP_STRIDE 68
#define KS_STRIDE 68
#define VS_STRIDE 72
#define KS_BUF (64*KS_STRIDE)
#define VS_BUF (64*VS_STRIDE)
#define ATT_SP_OFF   0
#define ATT_KS_OFF   (128*SP_STRIDE)
#define ATT_VS_OFF   (ATT_KS_OFF + 2*KS_BUF)
#define ATT_MA_OFF   (ATT_VS_OFF + 2*VS_BUF)
#define ATT_FAC_OFF  (ATT_MA_OFF + 128)
#define ATT_SMEM_FLOATS (ATT_FAC_OFF + 128)
#define ATT_SMEM_BYTES  (ATT_SMEM_FLOATS * 4)

__global__ __launch_bounds__(256, 2)
void attn_mma_kernel(const float* __restrict__ qkv, const int* __restrict__ mask,
                     float* __restrict__ out) {
    float*    SP   = dyn_sm + ATT_SP_OFF;
    float*    Ks   = dyn_sm + ATT_KS_OFF;
    float*    Vs   = dyn_sm + ATT_VS_OFF;
    float*    ma   = dyn_sm + ATT_MA_OFF;
    float*    facs = dyn_sm + ATT_FAC_OFF;
    uint32_t* SPu  = (uint32_t*)SP;
    uint32_t* Ksu  = (uint32_t*)Ks;
    uint32_t* Vsu  = (uint32_t*)Vs;

    int tid = threadIdx.x, lane = tid & 31, warp = tid >> 5;
    int b = blockIdx.z, h = blockIdx.y;
    int brow = blockIdx.x * 128;
    int g = lane >> 2, tg = lane & 3;
    int wr = warp * 16;
    int row_l = lane >> 1, half = lane & 1;

    int ld_r = tid >> 2, ld_c = (tid & 3) * 16;
    uint32_t kd0 = smem_u32(&Ks[ld_r * KS_STRIDE + ld_c]);
    uint32_t vd0 = smem_u32(&Vs[ld_r * VS_STRIDE + ld_c]);
    const uint32_t ks_buf_b = KS_BUF * 4, vs_buf_b = VS_BUF * 4;

    // stage Q raw bits
    {
        int row = tid >> 1, hf = tid & 1;
        const float* qp = qkv + ((size_t)(b * NN + brow + row)) * (3 * DIMC) + h * DD + hf * 32;
        uint32_t dst = smem_u32(&SP[row * SP_STRIDE + hf * 32]);
        #pragma unroll
        for (int i = 0; i < 8; i++)
            cp_async16(dst + i * 16, qp + i * 4);
        asm volatile("cp.async.commit_group;\n" ::);
        asm volatile("cp.async.wait_group 0;\n" ::);
    }
    __syncthreads();

    uint32_t aq[8][4];
    #pragma unroll
    for (int kk = 0; kk < 8; kk++) {
        aq[kk][0] = SPu[(wr + g) * SP_STRIDE + kk * 8 + tg] + TF_RND;
        aq[kk][1] = SPu[(wr + g + 8) * SP_STRIDE + kk * 8 + tg] + TF_RND;
        aq[kk][2] = SPu[(wr + g) * SP_STRIDE + kk * 8 + 4 + tg] + TF_RND;
        aq[kk][3] = SPu[(wr + g + 8) * SP_STRIDE + kk * 8 + 4 + tg] + TF_RND;
    }

    // prologue K/V tile 0
    {
        size_t base = ((size_t)(b * NN + ld_r)) * (3 * DIMC) + h * DD + ld_c;
        #pragma unroll
        for (int i = 0; i < 4; i++) {
            cp_async16(kd0 + i * 16, qkv + base + DIMC + i * 4);
            cp_async16(vd0 + i * 16, qkv + base + 2 * DIMC + i * 4);
        }
        asm volatile("cp.async.commit_group;\n" ::);
        if (tid < 64) ma[tid] = mask[b * NN + tid] ? 0.f : -1e30f;
    }

    float o[8][4];
    #pragma unroll
    for (int nt = 0; nt < 8; nt++)
        #pragma unroll
        for (int i = 0; i < 4; i++) o[nt][i] = 0.f;
    float m_run = -1e30f, l_run = 0.f;

    const int T = NN / 64;
    #pragma unroll 1
    for (int t = 0; t < T; t++) {
        int buf = t & 1;
        __syncthreads();

        if (t + 1 < T) {
            int nb = (t + 1) & 1;
            int k0n = (t + 1) * 64;
            size_t base = ((size_t)(b * NN + k0n + ld_r)) * (3 * DIMC) + h * DD + ld_c;
            #pragma unroll
            for (int i = 0; i < 4; i++) {
                cp_async16(kd0 + nb * ks_buf_b + i * 16, qkv + base + DIMC + i * 4);
                cp_async16(vd0 + nb * vs_buf_b + i * 16, qkv + base + 2 * DIMC + i * 4);
            }
            asm volatile("cp.async.commit_group;\n" ::);
            if (tid < 64) ma[nb * 64 + tid] = mask[b * NN + k0n + tid] ? 0.f : -1e30f;
            asm volatile("cp.async.wait_group 1;\n" ::);
        } else {
            asm volatile("cp.async.wait_group 0;\n" ::);
        }
        __syncthreads();

        const float* mab = ma + buf * 64;
        int kbase = buf * KS_BUF;
        int vbase = buf * VS_BUF;

        float s[8][4];
        #pragma unroll
        for (int nt = 0; nt < 8; nt++)
            #pragma unroll
            for (int i = 0; i < 4; i++) s[nt][i] = 0.f;
        #pragma unroll
        for (int kk = 0; kk < 8; kk++) {
            #pragma unroll
            for (int nt = 0; nt < 8; nt++) {
                uint32_t b0 = Ksu[kbase + (nt * 8 + g) * KS_STRIDE + kk * 8 + tg];
                uint32_t b1 = Ksu[kbase + (nt * 8 + g) * KS_STRIDE + kk * 8 + 4 + tg];
                mma_tf32(s[nt], aq[kk][0], aq[kk][1], aq[kk][2], aq[kk][3], b0, b1);
            }
        }
        #pragma unroll
        for (int nt = 0; nt < 8; nt++) {
            *(float2*)&SP[(wr + g) * SP_STRIDE + nt * 8 + 2 * tg]     = make_float2(s[nt][0], s[nt][1]);
            *(float2*)&SP[(wr + g + 8) * SP_STRIDE + nt * 8 + 2 * tg] = make_float2(s[nt][2], s[nt][3]);
        }
        __syncwarp();

        {
            float* srow = SP + (wr + row_l) * SP_STRIDE + half * 32;
            const float* mrow = mab + half * 32;
            float tm = -1e30f;
            #pragma unroll
            for (int j = 0; j < 32; j++)
                tm = fmaxf(tm, fmaf(srow[j], SCALE_ATT, mrow[j]));
            tm = fmaxf(tm, __shfl_xor_sync(0xffffffffu, tm, 1));
            float m_new = fmaxf(m_run, tm);
            float fac = __expf(m_run - m_new);
            float ps = 0.f;
            uint32_t* prow = (uint32_t*)srow;
            #pragma unroll
            for (int j = 0; j < 32; j++) {
                float p = __expf(fmaf(srow[j], SCALE_ATT, mrow[j]) - m_new);
                ps += p;
                prow[j] = f2tf(p);
            }
            ps += __shfl_xor_sync(0xffffffffu, ps, 1);
            l_run = l_run * fac + ps;
            m_run = m_new;
            if (half == 0) facs[wr + row_l] = fac;
        }
        __syncwarp();

        float fg  = facs[wr + g];
        float fg8 = facs[wr + g + 8];
        #pragma unroll
        for (int nt = 0; nt < 8; nt++) {
            o[nt][0] *= fg;  o[nt][1] *= fg;
            o[nt][2] *= fg8; o[nt][3] *= fg8;
        }
        #pragma unroll
        for (int kk = 0; kk < 8; kk++) {
            uint32_t a0 = SPu[(wr + g) * SP_STRIDE + kk * 8 + tg];
            uint32_t a1 = SPu[(wr + g + 8) * SP_STRIDE + kk * 8 + tg];
            uint32_t a2 = SPu[(wr + g) * SP_STRIDE + kk * 8 + 4 + tg];
            uint32_t a3 = SPu[(wr + g + 8) * SP_STRIDE + kk * 8 + 4 + tg];
            #pragma unroll
            for (int nt = 0; nt < 8; nt++) {
                uint32_t b0 = Vsu[vbase + (kk * 8 + tg) * VS_STRIDE + nt * 8 + g];
                uint32_t b1 = Vsu[vbase + (kk * 8 + tg + 4) * VS_STRIDE + nt * 8 + g];
                mma_tf32(o[nt], a0, a1, a2, a3, b0, b1);
            }
        }
    }

    if (half == 0) facs[wr + row_l] = l_run;
    __syncwarp();
    float il  = 1.0f / facs[wr + g];
    float il8 = 1.0f / facs[wr + g + 8];
    size_t r0 = ((size_t)(b * NN + brow + wr + g)) * DIMC + h * DD;
    size_t r8 = ((size_t)(b * NN + brow + wr + g + 8)) * DIMC + h * DD;
    // store output pre-rounded to tf32 bits (feeds proj GEMM A directly)
    #pragma unroll
    for (int nt = 0; nt < 8; nt++) {
        int col = nt * 8 + 2 * tg;
        *(uint2*)&out[r0 + col] = make_uint2(f2tf(o[nt][0] * il),  f2tf(o[nt][1] * il));
        *(uint2*)&out[r8 + col] = make_uint2(f2tf(o[nt][2] * il8), f2tf(o[nt][3] * il8));
    }
}

// ---------------- Launch ----------------
extern "C" void kernel_launch(void* const* d_in, const int* in_sizes, int n_in,
                              void* d_out, int out_size) {
    const float* x        = (const float*)d_in[0];
    const int*   mask     = (const int*)d_in[1];     // bool marshalled as int32
    const float* qkv_w    = (const float*)d_in[2];
    const float* CP_U_w   = (const float*)d_in[3];
    const float* CP_U_b   = (const float*)d_in[4];
    const float* CP_V_w   = (const float*)d_in[5];
    const float* CP_V_b   = (const float*)d_in[6];
    const float* CP_C     = (const float*)d_in[7];
    const float* CP_att   = (const float*)d_in[8];
    const float* proj_w   = (const float*)d_in[9];
    const float* proj_b   = (const float*)d_in[10];
    float* outp = (float*)d_out;

    float *p_qkv, *p_att, *p_WT, *p_Wc, *p_bqc, *p_bpc;
    cudaGetSymbolAddress((void**)&p_qkv, g_qkv);
    cudaGetSymbolAddress((void**)&p_att, g_att);
    cudaGetSymbolAddress((void**)&p_WT,  g_WT);
    cudaGetSymbolAddress((void**)&p_Wc,  g_Wc);
    cudaGetSymbolAddress((void**)&p_bqc, g_bqc);
    cudaGetSymbolAddress((void**)&p_bpc, g_bpc);

    static bool attr_set = false;
    if (!attr_set) {
        cudaFuncSetAttribute(attn_mma_kernel,
                             cudaFuncAttributeMaxDynamicSharedMemorySize, ATT_SMEM_BYTES);
        cudaFuncSetAttribute(gemm_nk_async<0>,
                             cudaFuncAttributeMaxDynamicSharedMemorySize, GEMM_NK_SMEM);
        cudaFuncSetAttribute(gemm_nk_async<1>,
                             cudaFuncAttributeMaxDynamicSharedMemorySize, GEMM_NK_SMEM);
        attr_set = true;
    }

    cpc_kernel<<<16, 256>>>(CP_C, CP_att);
    wfac_kernel<<<512, 256>>>(CP_V_w);
    biascomb_kernel<<<256, 256>>>(CP_U_b, CP_V_b, proj_b);

    // Fused combine: g_Wc = tf32_round(g_WT@CP_U_w + [qkv_w; proj_w])   K=64
    gemm_kn<<<dim3(4, 16), 256>>>(p_WT, RR, CP_U_w, RR,
                                  qkv_w, proj_w, 3 * DIMC,
                                  p_Wc, DIMC);

    // qkv = x @ Wcq^T + bqc     [8192,1536], K=512 (A rounded in-loop)
    gemm_nk_async<1><<<dim3(12, MTOT / 128), 256, GEMM_NK_SMEM>>>(x, DIMC, p_Wc, DIMC,
                                                                  p_bqc, p_qkv, 3 * DIMC);

    // tensor-core flash attention (output pre-rounded)
    attn_mma_kernel<<<dim3(NN / 128, HH, BB), 256, ATT_SMEM_BYTES>>>(p_qkv, mask, p_att);

    // proj = att @ Wcp^T + bpc  [8192,512], K=512 (A already rounded)
    gemm_nk_async<0><<<dim3(4, MTOT / 128), 256, GEMM_NK_SMEM>>>(p_att, DIMC,
                                                                 p_Wc + (size_t)3 * DIMC * DIMC, DIMC,
                                                                 p_bpc, outp, DIMC);
}

// round 15
// speedup vs baseline: 1.0731x; 1.0731x over previous
#include <cuda_runtime.h>
#include <cstdint>
#include <cstddef>

// ---------------- Problem constants ----------------
#define BB   8
#define NN   1024
#define DIMC 512
#define HH   8
#define DD   64
#define RR   64          // R1 = R2 = R = 64
#define MTOT (BB*NN)     // 8192
#define SCALE_ATT 0.125f // D^-0.5
#define S_CONST 1.0f

// ---------------- Scratch (__device__ globals; no allocation allowed) ----------------
__device__ float g_qkv  [(size_t)MTOT*3*DIMC];
__device__ float g_att  [(size_t)MTOT*DIMC];   // stored pre-rounded to tf32 bits
__device__ float g_CPc  [4*RR*RR];             // [f][ij]
__device__ float g_WT   [(3*DIMC+DIMC)*RR];    // rows 0..1535: WbigT, 1536..2047: WpT (xS)
__device__ float g_Wc   [(size_t)(3*DIMC+DIMC)*DIMC]; // tf32-rounded combined weights
__device__ float g_bqc  [3*DIMC];
__device__ float g_bpc  [DIMC];

// ---------------- Small precompute kernels ----------------
__global__ void cpc_kernel(const float* __restrict__ CP_C, const float* __restrict__ CP_att) {
    __shared__ float att_s[RR * 4];
    int tid = threadIdx.x;
    att_s[tid] = CP_att[tid];
    __syncthreads();
    int ij = blockIdx.x * 256 + tid;
    const float4* row = (const float4*)&CP_C[(size_t)ij << 6];
    float a0 = 0.f, a1 = 0.f, a2 = 0.f, a3 = 0.f;
    #pragma unroll
    for (int r4 = 0; r4 < 16; r4++) {
        float4 v = row[r4];
        const float* at = &att_s[r4 * 16];
        a0 += v.x * at[0]  + v.y * at[4]  + v.z * at[8]  + v.w * at[12];
        a1 += v.x * at[1]  + v.y * at[5]  + v.z * at[9]  + v.w * at[13];
        a2 += v.x * at[2]  + v.y * at[6]  + v.z * at[10] + v.w * at[14];
        a3 += v.x * at[3]  + v.y * at[7]  + v.z * at[11] + v.w * at[15];
    }
    g_CPc[0 * 4096 + ij] = a0;
    g_CPc[1 * 4096 + ij] = a1;
    g_CPc[2 * 4096 + ij] = a2;
    g_CPc[3 * 4096 + ij] = a3;
}

__global__ void wfac_kernel(const float* __restrict__ CP_V_w) {
    int idx = blockIdx.x * 256 + threadIdx.x;   // 131072
    int r = idx & 63;
    int o = idx >> 6;                           // 0..2047
    int f, d;
    if (o < 3 * DIMC) { f = o >> 9; d = o & 511; }
    else              { f = 3;      d = o - 3 * DIMC; }
    const float4* cp = (const float4*)&g_CPc[f * 4096 + r * RR];
    const float4* vw = (const float4*)&CP_V_w[(size_t)d * RR];
    float s = 0.f;
    #pragma unroll
    for (int i = 0; i < 16; i++) {
        float4 a = cp[i], b = vw[i];
        s += a.x * b.x + a.y * b.y + a.z * b.z + a.w * b.w;
    }
    g_WT[o * RR + r] = (o < 3 * DIMC) ? s : s * S_CONST;
}

__global__ void biascomb_kernel(const float* __restrict__ CP_U_b,
                                const float* __restrict__ CP_V_b,
                                const float* __restrict__ proj_b) {
    int w = blockIdx.x * 8 + (threadIdx.x >> 5);  // 0..2047
    int lane = threadIdx.x & 31;
    const float* row = &g_WT[w * RR];
    float s = CP_U_b[lane] * row[lane] + CP_U_b[lane + 32] * row[lane + 32];
    #pragma unroll
    for (int off = 16; off > 0; off >>= 1)
        s += __shfl_down_sync(0xffffffffu, s, off);
    if (lane == 0) {
        if (w < 3 * DIMC) g_bqc[w] = CP_V_b[w & 511] + s;
        else {
            int d = w - 3 * DIMC;
            g_bpc[d] = proj_b[d] + S_CONST * CP_V_b[d] + s;
        }
    }
}

// ---------------- tf32 helpers ----------------
__device__ __forceinline__ uint32_t f2tf(float x) {
    uint32_t r;
    asm("cvt.rna.tf32.f32 %0, %1;" : "=r"(r) : "f"(x));
    return r;
}
#define TF_RND 0x1000u   // RNA emulation for raw fp32 bits fed to tf32 mma

__device__ __forceinline__ void mma_tf32(float c[4], uint32_t a0, uint32_t a1,
                                         uint32_t a2, uint32_t a3,
                                         uint32_t b0, uint32_t b1) {
    asm volatile(
        "mma.sync.aligned.m16n8k8.row.col.f32.tf32.tf32.f32 "
        "{%0,%1,%2,%3}, {%4,%5,%6,%7}, {%8,%9}, {%0,%1,%2,%3};\n"
        : "+f"(c[0]), "+f"(c[1]), "+f"(c[2]), "+f"(c[3])
        : "r"(a0), "r"(a1), "r"(a2), "r"(a3), "r"(b0), "r"(b1));
}

__device__ __forceinline__ void cp_async16(uint32_t smem_addr, const void* gptr) {
    asm volatile("cp.async.ca.shared.global [%0], [%1], 16;\n"
                 :: "r"(smem_addr), "l"(gptr));
}
__device__ __forceinline__ void cp_async16_cg(uint32_t smem_addr, const void* gptr) {
    asm volatile("cp.async.cg.shared.global [%0], [%1], 16;\n"
                 :: "r"(smem_addr), "l"(gptr));
}
__device__ __forceinline__ uint32_t smem_u32(const void* p) {
    return (uint32_t)__cvta_generic_to_shared(p);
}

extern __shared__ float dyn_sm[];

// ---------------- cp.async 3-stage tf32 GEMM, BK=16 (round-12 proven shape) ----------------
// B in [N,K], tf32-prerounded. RA=1: round A fragments in-loop. RA=0: A prerounded.
#define GST 20
#define STAGE_W (128*GST)
#define GEMM_NK_SMEM ((3*STAGE_W*2) * 4)

template<int RA>
__global__ __launch_bounds__(256, 2)
void gemm_nk_async(const float* __restrict__ A, int lda,
                   const float* __restrict__ B, int K,
                   const float* __restrict__ bias,
                   float* __restrict__ C, int N) {
    float* As = dyn_sm;
    float* Bs = dyn_sm + 3 * STAGE_W;

    int tid  = threadIdx.x;
    int lane = tid & 31;
    int warp = tid >> 5;
    int warp_m = (warp >> 2) * 64;
    int warp_n = (warp & 3) * 32;
    int bm0 = blockIdx.y * 128;
    int bn0 = blockIdx.x * 128;
    int lr = lane >> 2;
    int lc = lane & 3;

    float acc[4][4][4];
    #pragma unroll
    for (int i = 0; i < 4; i++)
        #pragma unroll
        for (int j = 0; j < 4; j++)
            #pragma unroll
            for (int k = 0; k < 4; k++) acc[i][j][k] = 0.f;

    int a_m = tid >> 2;                // 0..63
    int a_k = (tid & 3) * 4;           // 0,4,8,12
    const float* pa0 = &A[(size_t)(bm0 + a_m) * lda + a_k];
    const float* pa1 = &A[(size_t)(bm0 + a_m + 64) * lda + a_k];
    uint32_t sa0 = smem_u32(&As[a_m * GST + a_k]);
    uint32_t sa1 = smem_u32(&As[(a_m + 64) * GST + a_k]);

    int b_n = tid >> 1;                // 0..127
    int b_k = (tid & 1) * 8;           // 0 or 8
    const float* pb = &B[(size_t)(bn0 + b_n) * K + b_k];
    uint32_t sb0 = smem_u32(&Bs[b_n * GST + b_k]);

    const uint32_t stage_bytes = STAGE_W * 4;

    #pragma unroll
    for (int s = 0; s < 2; s++) {
        int k0 = s * 16;
        cp_async16_cg(sa0 + s * stage_bytes, pa0 + k0);
        cp_async16_cg(sa1 + s * stage_bytes, pa1 + k0);
        cp_async16_cg(sb0 + s * stage_bytes, pb + k0);
        cp_async16_cg(sb0 + s * stage_bytes + 16, pb + k0 + 4);
        asm volatile("cp.async.commit_group;\n" ::);
    }

    int T = K / 16;
    uint32_t* Asu = (uint32_t*)As;
    uint32_t* Bsu = (uint32_t*)Bs;

    #pragma unroll 1
    for (int t = 0; t < T; t++) {
        int p = t % 3;
        asm volatile("cp.async.wait_group 1;\n" ::);
        __syncthreads();

        int tn = t + 2;
        if (tn < T) {
            int s = tn % 3;
            int k0 = tn * 16;
            cp_async16_cg(sa0 + s * stage_bytes, pa0 + k0);
            cp_async16_cg(sa1 + s * stage_bytes, pa1 + k0);
            cp_async16_cg(sb0 + s * stage_bytes, pb + k0);
            cp_async16_cg(sb0 + s * stage_bytes + 16, pb + k0 + 4);
        }
        asm volatile("cp.async.commit_group;\n" ::);

        int pbase = p * STAGE_W;
        #pragma unroll
        for (int kk = 0; kk < 16; kk += 8) {
            uint32_t af[4][4], bf[4][2];
            #pragma unroll
            for (int mt = 0; mt < 4; mt++) {
                int r = warp_m + mt * 16 + lr;
                af[mt][0] = Asu[pbase + r * GST + kk + lc];
                af[mt][1] = Asu[pbase + (r + 8) * GST + kk + lc];
                af[mt][2] = Asu[pbase + r * GST + kk + 4 + lc];
                af[mt][3] = Asu[pbase + (r + 8) * GST + kk + 4 + lc];
                if (RA) {
                    af[mt][0] += TF_RND; af[mt][1] += TF_RND;
                    af[mt][2] += TF_RND; af[mt][3] += TF_RND;
                }
            }
            #pragma unroll
            for (int nt = 0; nt < 4; nt++) {
                int c = warp_n + nt * 8 + lr;
                bf[nt][0] = Bsu[pbase + c * GST + kk + lc];
                bf[nt][1] = Bsu[pbase + c * GST + kk + 4 + lc];
            }
            #pragma unroll
            for (int mt = 0; mt < 4; mt++)
                #pragma unroll
                for (int nt = 0; nt < 4; nt++)
                    mma_tf32(acc[mt][nt], af[mt][0], af[mt][1], af[mt][2], af[mt][3],
                             bf[nt][0], bf[nt][1]);
        }
    }

    #pragma unroll
    for (int mt = 0; mt < 4; mt++) {
        int row = bm0 + warp_m + mt * 16 + lr;
        #pragma unroll
        for (int nt = 0; nt < 4; nt++) {
            int col = bn0 + warp_n + nt * 8 + lc * 2;
            float b0 = bias[col], b1 = bias[col + 1];
            *(float2*)&C[(size_t)row * N + col] =
                make_float2(acc[mt][nt][0] + b0, acc[mt][nt][1] + b1);
            *(float2*)&C[(size_t)(row + 8) * N + col] =
                make_float2(acc[mt][nt][2] + b0, acc[mt][nt][3] + b1);
        }
    }
}

// ---------------- Combine GEMM (B in [K,N], split Cadd; output tf32-rounded) ----------------
__global__ __launch_bounds__(256, 2)
void gemm_kn(const float* __restrict__ A, int lda,
             const float* __restrict__ B, int K,
             const float* __restrict__ Cadd, const float* __restrict__ Cadd2,
             int cadd_split,
             float* __restrict__ C, int N) {
    __shared__ uint32_t As[2][128][20];
    __shared__ uint32_t Bs[2][128][20];

    int tid  = threadIdx.x;
    int lane = tid & 31;
    int warp = tid >> 5;
    int warp_m = (warp >> 2) * 64;
    int warp_n = (warp & 3) * 32;
    int bm0 = blockIdx.y * 128;
    int bn0 = blockIdx.x * 128;
    int lr = lane >> 2;
    int lc = lane & 3;

    float acc[4][4][4];
    #pragma unroll
    for (int i = 0; i < 4; i++)
        #pragma unroll
        for (int j = 0; j < 4; j++)
            #pragma unroll
            for (int k = 0; k < 4; k++) acc[i][j][k] = 0.f;

    int a_m = tid >> 2;
    int a_k = (tid & 3) * 4;
    const float* pa0 = &A[(size_t)(bm0 + a_m) * lda + a_k];
    const float* pa1 = &A[(size_t)(bm0 + a_m + 64) * lda + a_k];

    int bkn_k = tid >> 4;
    int bkn_n = (tid & 15) * 8;
    const float* pb_kn = &B[(size_t)bkn_k * N + bn0 + bkn_n];

    float4 av0, av1, bv0, bv1;
    av0 = *(const float4*)pa0;
    av1 = *(const float4*)pa1;
    bv0 = *(const float4*)pb_kn;
    bv1 = *(const float4*)(pb_kn + 4);
    {
        *(uint4*)&As[0][a_m][a_k]      = make_uint4(f2tf(av0.x), f2tf(av0.y), f2tf(av0.z), f2tf(av0.w));
        *(uint4*)&As[0][a_m + 64][a_k] = make_uint4(f2tf(av1.x), f2tf(av1.y), f2tf(av1.z), f2tf(av1.w));
        Bs[0][bkn_n + 0][bkn_k] = f2tf(bv0.x);
        Bs[0][bkn_n + 1][bkn_k] = f2tf(bv0.y);
        Bs[0][bkn_n + 2][bkn_k] = f2tf(bv0.z);
        Bs[0][bkn_n + 3][bkn_k] = f2tf(bv0.w);
        Bs[0][bkn_n + 4][bkn_k] = f2tf(bv1.x);
        Bs[0][bkn_n + 5][bkn_k] = f2tf(bv1.y);
        Bs[0][bkn_n + 6][bkn_k] = f2tf(bv1.z);
        Bs[0][bkn_n + 7][bkn_k] = f2tf(bv1.w);
    }
    __syncthreads();

    int T = K / 16;
    #pragma unroll 1
    for (int t = 0; t < T; t++) {
        int p = t & 1;
        if (t + 1 < T) {
            int k0 = (t + 1) * 16;
            av0 = *(const float4*)(pa0 + k0);
            av1 = *(const float4*)(pa1 + k0);
            bv0 = *(const float4*)(pb_kn + (size_t)k0 * N);
            bv1 = *(const float4*)(pb_kn + (size_t)k0 * N + 4);
        }

        #pragma unroll
        for (int kk = 0; kk < 16; kk += 8) {
            uint32_t af[4][4], bf[4][2];
            #pragma unroll
            for (int mt = 0; mt < 4; mt++) {
                int r = warp_m + mt * 16 + lr;
                af[mt][0] = As[p][r][kk + lc];
                af[mt][1] = As[p][r + 8][kk + lc];
                af[mt][2] = As[p][r][kk + 4 + lc];
                af[mt][3] = As[p][r + 8][kk + 4 + lc];
            }
            #pragma unroll
            for (int nt = 0; nt < 4; nt++) {
                int c = warp_n + nt * 8 + lr;
                bf[nt][0] = Bs[p][c][kk + lc];
                bf[nt][1] = Bs[p][c][kk + 4 + lc];
            }
            #pragma unroll
            for (int mt = 0; mt < 4; mt++)
                #pragma unroll
                for (int nt = 0; nt < 4; nt++)
                    mma_tf32(acc[mt][nt], af[mt][0], af[mt][1], af[mt][2], af[mt][3],
                             bf[nt][0], bf[nt][1]);
        }

        if (t + 1 < T) {
            int q = 1 - p;
            *(uint4*)&As[q][a_m][a_k]      = make_uint4(f2tf(av0.x), f2tf(av0.y), f2tf(av0.z), f2tf(av0.w));
            *(uint4*)&As[q][a_m + 64][a_k] = make_uint4(f2tf(av1.x), f2tf(av1.y), f2tf(av1.z), f2tf(av1.w));
            Bs[q][bkn_n + 0][bkn_k] = f2tf(bv0.x);
            Bs[q][bkn_n + 1][bkn_k] = f2tf(bv0.y);
            Bs[q][bkn_n + 2][bkn_k] = f2tf(bv0.z);
            Bs[q][bkn_n + 3][bkn_k] = f2tf(bv0.w);
            Bs[q][bkn_n + 4][bkn_k] = f2tf(bv1.x);
            Bs[q][bkn_n + 5][bkn_k] = f2tf(bv1.y);
            Bs[q][bkn_n + 6][bkn_k] = f2tf(bv1.z);
            Bs[q][bkn_n + 7][bkn_k] = f2tf(bv1.w);
        }
        __syncthreads();
    }

    // Epilogue: split Cadd add, then round to tf32 bits (these feed mma B later)
    #pragma unroll
    for (int mt = 0; mt < 4; mt++) {
        int row = bm0 + warp_m + mt * 16 + lr;
        #pragma unroll
        for (int nt = 0; nt < 4; nt++) {
            int col = bn0 + warp_n + nt * 8 + lc * 2;
            const float* ca  = (row < cadd_split) ? &Cadd[(size_t)row * N]
                                                  : &Cadd2[(size_t)(row - cadd_split) * N];
            const float* ca8 = (row < cadd_split) ? &Cadd[(size_t)(row + 8) * N]
                                                  : &Cadd2[(size_t)(row + 8 - cadd_split) * N];
            float2 c0 = *(const float2*)&ca[col];
            float2 c1 = *(const float2*)&ca8[col];
            uint2 v0 = make_uint2(f2tf(acc[mt][nt][0] + c0.x), f2tf(acc[mt][nt][1] + c0.y));
            uint2 v1 = make_uint2(f2tf(acc[mt][nt][2] + c1.x), f2tf(acc[mt][nt][3] + c1.y));
            *(uint2*)&C[(size_t)row * N + col] = v0;
            *(uint2*)&C[(size_t)(row + 8) * N + col] = v1;
        }
    }
}

// ---------------- Tensor-core flash attention (double-buffered K/V cp.async) ----------------
#define SP_STRIDE 68
#define KS_STRIDE 68
#define VS_STRIDE 72
#define KS_BUF (64*KS_STRIDE)
#define VS_BUF (64*VS_STRIDE)
#define ATT_SP_OFF   0
#define ATT_KS_OFF   (128*SP_STRIDE)
#define ATT_VS_OFF   (ATT_KS_OFF + 2*KS_BUF)
#define ATT_MA_OFF   (ATT_VS_OFF + 2*VS_BUF)
#define ATT_FAC_OFF  (ATT_MA_OFF + 128)
#define ATT_SMEM_FLOATS (ATT_FAC_OFF + 128)
#define ATT_SMEM_BYTES  (ATT_SMEM_FLOATS * 4)

__global__ __launch_bounds__(256, 2)
void attn_mma_kernel(const float* __restrict__ qkv, const int* __restrict__ mask,
                     float* __restrict__ out) {
    float*    SP   = dyn_sm + ATT_SP_OFF;
    float*    Ks   = dyn_sm + ATT_KS_OFF;
    float*    Vs   = dyn_sm + ATT_VS_OFF;
    float*    ma   = dyn_sm + ATT_MA_OFF;
    float*    facs = dyn_sm + ATT_FAC_OFF;
    uint32_t* SPu  = (uint32_t*)SP;
    uint32_t* Ksu  = (uint32_t*)Ks;
    uint32_t* Vsu  = (uint32_t*)Vs;

    int tid = threadIdx.x, lane = tid & 31, warp = tid >> 5;
    int b = blockIdx.z, h = blockIdx.y;
    int brow = blockIdx.x * 128;
    int g = lane >> 2, tg = lane & 3;
    int wr = warp * 16;
    int row_l = lane >> 1, half = lane & 1;

    int ld_r = tid >> 2, ld_c = (tid & 3) * 16;
    uint32_t kd0 = smem_u32(&Ks[ld_r * KS_STRIDE + ld_c]);
    uint32_t vd0 = smem_u32(&Vs[ld_r * VS_STRIDE + ld_c]);
    const uint32_t ks_buf_b = KS_BUF * 4, vs_buf_b = VS_BUF * 4;

    // stage Q raw bits
    {
        int row = tid >> 1, hf = tid & 1;
        const float* qp = qkv + ((size_t)(b * NN + brow + row)) * (3 * DIMC) + h * DD + hf * 32;
        uint32_t dst = smem_u32(&SP[row * SP_STRIDE + hf * 32]);
        #pragma unroll
        for (int i = 0; i < 8; i++)
            cp_async16(dst + i * 16, qp + i * 4);
        asm volatile("cp.async.commit_group;\n" ::);
        asm volatile("cp.async.wait_group 0;\n" ::);
    }
    __syncthreads();

    uint32_t aq[8][4];
    #pragma unroll
    for (int kk = 0; kk < 8; kk++) {
        aq[kk][0] = SPu[(wr + g) * SP_STRIDE + kk * 8 + tg] + TF_RND;
        aq[kk][1] = SPu[(wr + g + 8) * SP_STRIDE + kk * 8 + tg] + TF_RND;
        aq[kk][2] = SPu[(wr + g) * SP_STRIDE + kk * 8 + 4 + tg] + TF_RND;
        aq[kk][3] = SPu[(wr + g + 8) * SP_STRIDE + kk * 8 + 4 + tg] + TF_RND;
    }

    // prologue K/V tile 0
    {
        size_t base = ((size_t)(b * NN + ld_r)) * (3 * DIMC) + h * DD + ld_c;
        #pragma unroll
        for (int i = 0; i < 4; i++) {
            cp_async16(kd0 + i * 16, qkv + base + DIMC + i * 4);
            cp_async16(vd0 + i * 16, qkv + base + 2 * DIMC + i * 4);
        }
        asm volatile("cp.async.commit_group;\n" ::);
        if (tid < 64) ma[tid] = mask[b * NN + tid] ? 0.f : -1e30f;
    }

    float o[8][4];
    #pragma unroll
    for (int nt = 0; nt < 8; nt++)
        #pragma unroll
        for (int i = 0; i < 4; i++) o[nt][i] = 0.f;
    float m_run = -1e30f, l_run = 0.f;

    const int T = NN / 64;
    #pragma unroll 1
    for (int t = 0; t < T; t++) {
        int buf = t & 1;
        __syncthreads();

        if (t + 1 < T) {
            int nb = (t + 1) & 1;
            int k0n = (t + 1) * 64;
            size_t base = ((size_t)(b * NN + k0n + ld_r)) * (3 * DIMC) + h * DD + ld_c;
            #pragma unroll
            for (int i = 0; i < 4; i++) {
                cp_async16(kd0 + nb * ks_buf_b + i * 16, qkv + base + DIMC + i * 4);
                cp_async16(vd0 + nb * vs_buf_b + i * 16, qkv + base + 2 * DIMC + i * 4);
            }
            asm volatile("cp.async.commit_group;\n" ::);
            if (tid < 64) ma[nb * 64 + tid] = mask[b * NN + k0n + tid] ? 0.f : -1e30f;
            asm volatile("cp.async.wait_group 1;\n" ::);
        } else {
            asm volatile("cp.async.wait_group 0;\n" ::);
        }
        __syncthreads();

        const float* mab = ma + buf * 64;
        int kbase = buf * KS_BUF;
        int vbase = buf * VS_BUF;

        float s[8][4];
        #pragma unroll
        for (int nt = 0; nt < 8; nt++)
            #pragma unroll
            for (int i = 0; i < 4; i++) s[nt][i] = 0.f;
        #pragma unroll
        for (int kk = 0; kk < 8; kk++) {
            #pragma unroll
            for (int nt = 0; nt < 8; nt++) {
                uint32_t b0 = Ksu[kbase + (nt * 8 + g) * KS_STRIDE + kk * 8 + tg];
                uint32_t b1 = Ksu[kbase + (nt * 8 + g) * KS_STRIDE + kk * 8 + 4 + tg];
                mma_tf32(s[nt], aq[kk][0], aq[kk][1], aq[kk][2], aq[kk][3], b0, b1);
            }
        }
        #pragma unroll
        for (int nt = 0; nt < 8; nt++) {
            *(float2*)&SP[(wr + g) * SP_STRIDE + nt * 8 + 2 * tg]     = make_float2(s[nt][0], s[nt][1]);
            *(float2*)&SP[(wr + g + 8) * SP_STRIDE + nt * 8 + 2 * tg] = make_float2(s[nt][2], s[nt][3]);
        }
        __syncwarp();

        {
            float* srow = SP + (wr + row_l) * SP_STRIDE + half * 32;
            const float* mrow = mab + half * 32;
            float tm = -1e30f;
            #pragma unroll
            for (int j = 0; j < 32; j++)
                tm = fmaxf(tm, fmaf(srow[j], SCALE_ATT, mrow[j]));
            tm = fmaxf(tm, __shfl_xor_sync(0xffffffffu, tm, 1));
            float m_new = fmaxf(m_run, tm);
            float fac = __expf(m_run - m_new);
            float ps = 0.f;
            uint32_t* prow = (uint32_t*)srow;
            #pragma unroll
            for (int j = 0; j < 32; j++) {
                float p = __expf(fmaf(srow[j], SCALE_ATT, mrow[j]) - m_new);
                ps += p;
                prow[j] = f2tf(p);
            }
            ps += __shfl_xor_sync(0xffffffffu, ps, 1);
            l_run = l_run * fac + ps;
            m_run = m_new;
            if (half == 0) facs[wr + row_l] = fac;
        }
        __syncwarp();

        float fg  = facs[wr + g];
        float fg8 = facs[wr + g + 8];
        #pragma unroll
        for (int nt = 0; nt < 8; nt++) {
            o[nt][0] *= fg;  o[nt][1] *= fg;
            o[nt][2] *= fg8; o[nt][3] *= fg8;
        }
        #pragma unroll
        for (int kk = 0; kk < 8; kk++) {
            uint32_t a0 = SPu[(wr + g) * SP_STRIDE + kk * 8 + tg];
            uint32_t a1 = SPu[(wr + g + 8) * SP_STRIDE + kk * 8 + tg];
            uint32_t a2 = SPu[(wr + g) * SP_STRIDE + kk * 8 + 4 + tg];
            uint32_t a3 = SPu[(wr + g + 8) * SP_STRIDE + kk * 8 + 4 + tg];
            #pragma unroll
            for (int nt = 0; nt < 8; nt++) {
                uint32_t b0 = Vsu[vbase + (kk * 8 + tg) * VS_STRIDE + nt * 8 + g];
                uint32_t b1 = Vsu[vbase + (kk * 8 + tg + 4) * VS_STRIDE + nt * 8 + g];
                mma_tf32(o[nt], a0, a1, a2, a3, b0, b1);
            }
        }
    }

    if (half == 0) facs[wr + row_l] = l_run;
    __syncwarp();
    float il  = 1.0f / facs[wr + g];
    float il8 = 1.0f / facs[wr + g + 8];
    size_t r0 = ((size_t)(b * NN + brow + wr + g)) * DIMC + h * DD;
    size_t r8 = ((size_t)(b * NN + brow + wr + g + 8)) * DIMC + h * DD;
    // store output pre-rounded to tf32 bits (feeds proj GEMM A directly, RA=0)
    #pragma unroll
    for (int nt = 0; nt < 8; nt++) {
        int col = nt * 8 + 2 * tg;
        *(uint2*)&out[r0 + col] = make_uint2(f2tf(o[nt][0] * il),  f2tf(o[nt][1] * il));
        *(uint2*)&out[r8 + col] = make_uint2(f2tf(o[nt][2] * il8), f2tf(o[nt][3] * il8));
    }
}

// ---------------- Launch ----------------
extern "C" void kernel_launch(void* const* d_in, const int* in_sizes, int n_in,
                              void* d_out, int out_size) {
    const float* x        = (const float*)d_in[0];
    const int*   mask     = (const int*)d_in[1];     // bool marshalled as int32
    const float* qkv_w    = (const float*)d_in[2];
    const float* CP_U_w   = (const float*)d_in[3];
    const float* CP_U_b   = (const float*)d_in[4];
    const float* CP_V_w   = (const float*)d_in[5];
    const float* CP_V_b   = (const float*)d_in[6];
    const float* CP_C     = (const float*)d_in[7];
    const float* CP_att   = (const float*)d_in[8];
    const float* proj_w   = (const float*)d_in[9];
    const float* proj_b   = (const float*)d_in[10];
    float* outp = (float*)d_out;

    float *p_qkv, *p_att, *p_WT, *p_Wc, *p_bqc, *p_bpc;
    cudaGetSymbolAddress((void**)&p_qkv, g_qkv);
    cudaGetSymbolAddress((void**)&p_att, g_att);
    cudaGetSymbolAddress((void**)&p_WT,  g_WT);
    cudaGetSymbolAddress((void**)&p_Wc,  g_Wc);
    cudaGetSymbolAddress((void**)&p_bqc, g_bqc);
    cudaGetSymbolAddress((void**)&p_bpc, g_bpc);

    static bool attr_set = false;
    if (!attr_set) {
        cudaFuncSetAttribute(attn_mma_kernel,
                             cudaFuncAttributeMaxDynamicSharedMemorySize, ATT_SMEM_BYTES);
        cudaFuncSetAttribute(gemm_nk_async<0>,
                             cudaFuncAttributeMaxDynamicSharedMemorySize, GEMM_NK_SMEM);
        cudaFuncSetAttribute(gemm_nk_async<1>,
                             cudaFuncAttributeMaxDynamicSharedMemorySize, GEMM_NK_SMEM);
        attr_set = true;
    }

    cpc_kernel<<<16, 256>>>(CP_C, CP_att);
    wfac_kernel<<<512, 256>>>(CP_V_w);
    biascomb_kernel<<<256, 256>>>(CP_U_b, CP_V_b, proj_b);

    // Fused combine: g_Wc = tf32_round(g_WT@CP_U_w + [qkv_w; proj_w])   K=64
    gemm_kn<<<dim3(4, 16), 256>>>(p_WT, RR, CP_U_w, RR,
                                  qkv_w, proj_w, 3 * DIMC,
                                  p_Wc, DIMC);

    // qkv = x @ Wcq^T + bqc     [8192,1536], K=512 (A rounded in-loop)
    gemm_nk_async<1><<<dim3(12, MTOT / 128), 256, GEMM_NK_SMEM>>>(x, DIMC, p_Wc, DIMC,
                                                                  p_bqc, p_qkv, 3 * DIMC);

    // tensor-core flash attention (output pre-rounded)
    attn_mma_kernel<<<dim3(NN / 128, HH, BB), 256, ATT_SMEM_BYTES>>>(p_qkv, mask, p_att);

    // proj = att @ Wcp^T + bpc  [8192,512], K=512 (A already rounded)
    gemm_nk_async<0><<<dim3(4, MTOT / 128), 256, GEMM_NK_SMEM>>>(p_att, DIMC,
                                                                 p_Wc + (size_t)3 * DIMC * DIMC, DIMC,
                                                                 p_bpc, outp, DIMC);
}